// round 5
// baseline (speedup 1.0000x reference)
#include <cuda_runtime.h>
#include <math.h>

// Problem dims
#define BB 4
#define CC 16
#define FP 10
#define FA 30
#define SSEG 4
#define TT 2048
#define NBINS 18

#define NTH 256          // 8 warps
#define NCOPY 4          // 4 accumulator copies (warp pairs share one)
#define CHUNK 512        // amp t-chunk staged in smem

// Shared memory layout (bytes)
#define ACC_FLOATS (NCOPY*FP*NBINS*32)          // 23040 floats = 92160 B
#define ACC_OFF    0
#define AMP_OFF    (ACC_FLOATS*4)               // 92160
#define AMP_FLOATS (32*(CHUNK+1))               // 16416 floats = 65664 B
#define BIN_OFF    (AMP_OFF + AMP_FLOATS*4)     // 157824 (16B aligned)
#define CNT_OFF    (BIN_OFF + TT*16)            // 190592
#define SMEM_BYTES (CNT_OFF + FP*NBINS*4)       // 191312

// Scratch: per-segment MI partials (B,C,Fp,Fa,S)
__device__ float g_partial[BB*CC*FP*FA*SSEG];

__global__ __launch_bounds__(NTH, 1)
void mi_partial_kernel(const float* __restrict__ pha, const float* __restrict__ amp)
{
    extern __shared__ unsigned char smem[];
    float* acc           = (float*)(smem + ACC_OFF);   // [copy][p][k][32]
    float* ampch         = (float*)(smem + AMP_OFF);   // [a(32)][CHUNK+1]
    unsigned char* binpk = smem + BIN_OFF;             // [t][16] packed bins
    int* cnt             = (int*)(smem + CNT_OFF);     // [p][k]

    const int bcs = blockIdx.x;           // ((b*CC + c)*SSEG + s)
    const int s   = bcs & 3;
    const int bc  = bcs >> 2;
    const int tid  = threadIdx.x;
    const int w    = tid >> 5;
    const int lane = tid & 31;

    const long phaBase = (long)bc * FP * (SSEG*TT) + (long)s * TT;
    const long ampBase = (long)bc * FA * (SSEG*TT) + (long)s * TT;

    // ---- zero accumulators / counts ----
    for (int i = tid; i < ACC_FLOATS; i += NTH) acc[i] = 0.f;
    for (int i = tid; i < FP*NBINS;   i += NTH) cnt[i] = 0;
    __syncthreads();

    // ---- phase 1: bins (exact searchsorted replication) + counts ----
    const float PI_F = 3.14159265358979323846f;        // rounds to f32(pi)
    const float step = __fdiv_rn(2.0f * PI_F, (float)NBINS); // (stop-start)/18, rn
    const float inv_step = 1.0f / step;                 // guess only
    for (int i = tid; i < FP*TT; i += NTH) {
        int p = i >> 11;                 // TT = 2048
        int t = i & (TT - 1);
        float v = pha[phaBase + (long)p * (SSEG*TT) + t];
        int k = (int)floorf((v + PI_F) * inv_step);
        k = min(max(k, 0), NBINS - 1);
        // fixup against exact cutoffs c[i] = -PI + i*step (mul,add each rn, no fma)
        #pragma unroll
        for (int it = 0; it < 2; ++it) {
            float ck  = __fadd_rn(-PI_F, __fmul_rn((float)k,       step));
            float ck1 = __fadd_rn(-PI_F, __fmul_rn((float)(k + 1), step));
            if (k > 0 && v <= ck)                 k--;
            else if (k < NBINS - 1 && v > ck1)    k++;
        }
        binpk[t * 16 + p] = (unsigned char)k;
        atomicAdd(&cnt[p * NBINS + k], 1);
    }
    __syncthreads();

    // ---- phase 2: chunked scatter-accumulate ----
    const int jcp  = w >> 1;             // accumulator copy 0..3
    const int psub = (w & 1) * 5;        // even warp: p 0-4, odd warp: p 5-9
    const int accWarpBase = ((jcp * FP + psub) * NBINS) * 32 + lane;

    for (int t0 = 0; t0 < TT; t0 += CHUNK) {
        // stage amp chunk: coalesced gmem reads, conflict-free smem writes
        #pragma unroll
        for (int rep = 0; rep < (FA * CHUNK) / NTH; ++rep) {
            int i  = rep * NTH + tid;
            int a  = i >> 9;             // CHUNK = 512
            int tc = i & (CHUNK - 1);
            ampch[a * (CHUNK + 1) + tc] =
                amp[ampBase + (long)a * (SSEG*TT) + t0 + tc];
        }
        __syncthreads();

        for (int tc = jcp; tc < CHUNK; tc += NCOPY) {
            // broadcast: all 10 bins for this t in one LDS.128
            const uint4 bp = *reinterpret_cast<const uint4*>(binpk + (t0 + tc) * 16);
            // conflict-free: bank = (lane*513 + tc) % 32 distinct per lane
            float val = ampch[lane * (CHUNK + 1) + tc];

            int bn0, bn1, bn2, bn3, bn4;
            if ((w & 1) == 0) {
                bn0 =  bp.x        & 255; bn1 = (bp.x >> 8)  & 255;
                bn2 = (bp.x >> 16) & 255; bn3 = (bp.x >> 24) & 255;
                bn4 =  bp.y        & 255;
            } else {
                bn0 = (bp.y >> 8)  & 255; bn1 = (bp.y >> 16) & 255;
                bn2 = (bp.y >> 24) & 255; bn3 =  bp.z        & 255;
                bn4 = (bp.z >> 8)  & 255;
            }
            // bank = lane for every access: zero conflicts, no races
            acc[accWarpBase + (0 * NBINS + bn0) * 32] += val;
            acc[accWarpBase + (1 * NBINS + bn1) * 32] += val;
            acc[accWarpBase + (2 * NBINS + bn2) * 32] += val;
            acc[accWarpBase + (3 * NBINS + bn3) * 32] += val;
            acc[accWarpBase + (4 * NBINS + bn4) * 32] += val;
        }
        __syncthreads();
    }

    // ---- phase 3: epilogue per (p,a) ----
    for (int idx = tid; idx < FP * FA; idx += NTH) {
        int p = idx / FA;
        int a = idx - p * FA;
        float meanv[NBINS];
        float tot = 0.f;
        #pragma unroll
        for (int k = 0; k < NBINS; ++k) {
            float sv = 0.f;
            #pragma unroll
            for (int cpy = 0; cpy < NCOPY; ++cpy)
                sv += acc[((cpy * FP + p) * NBINS + k) * 32 + a];
            float m = sv / ((float)cnt[p * NBINS + k] + 1e-9f);
            meanv[k] = m;
            tot += m;
        }
        float inv = 1.0f / (tot + 1e-9f);
        float ent = 0.f;
        #pragma unroll
        for (int k = 0; k < NBINS; ++k) {
            float pr = meanv[k] * inv;
            ent += pr * logf(pr + 1e-9f);
        }
        const float L18 = 2.8903717578961645f;  // log(18)
        float MI = (L18 + ent) / L18;
        g_partial[((long)(bc * FP + p) * FA + a) * SSEG + s] = MI;
    }
}

__global__ void mi_mean_kernel(float* __restrict__ out)
{
    int i = blockIdx.x * blockDim.x + threadIdx.x;
    if (i < BB*CC*FP*FA) {
        const float* p = g_partial + (long)i * SSEG;
        out[i] = (p[0] + p[1] + p[2] + p[3]) * 0.25f;
    }
}

extern "C" void kernel_launch(void* const* d_in, const int* in_sizes, int n_in,
                              void* d_out, int out_size)
{
    const float* pha = (const float*)d_in[0];
    const float* amp = (const float*)d_in[1];
    // defensive: pha has fewer elements than amp
    if (n_in >= 2 && in_sizes[0] > in_sizes[1]) {
        const float* t = pha; pha = amp; amp = t;
    }
    (void)cudaFuncSetAttribute(mi_partial_kernel,
                               cudaFuncAttributeMaxDynamicSharedMemorySize, SMEM_BYTES);
    mi_partial_kernel<<<BB*CC*SSEG, NTH, SMEM_BYTES>>>(pha, amp);
    mi_mean_kernel<<<(BB*CC*FP*FA + 255) / 256, 256>>>((float*)d_out);
}

// round 6
// speedup vs baseline: 1.5349x; 1.5349x over previous
#include <cuda_runtime.h>
#include <math.h>

// Problem dims
#define BB 4
#define CC 16
#define FP 10
#define FA 30
#define SSEG 4
#define TT 2048
#define NBINS 18

#define NTH 512          // 16 warps
#define NCOPY 4          // 4 accumulator copies (one per warp-quad)
#define CHUNK 512        // amp t-chunk staged in smem

// amp chunk: stride 516 floats per a-row, permuted tc -> (tc&3)*128 + (tc>>2)
#define AMP_STRIDE 516
#define AMP_FLOATS (32*AMP_STRIDE)              // 16512 floats (rows 30/31 zero)

// Shared memory layout (bytes)
#define ACC_FLOATS (NCOPY*FP*NBINS*32)          // 23040 floats = 92160 B
#define ACC_OFF    0
#define AMP_OFF    (ACC_FLOATS*4)               // 92160
#define BIN_OFF    (AMP_OFF + AMP_FLOATS*4)     // 158208 (16B aligned)
#define BIN_BYTES  (4*4*512*4)                  // [g][c][t4][4] = 32768
#define SMEM_BYTES (BIN_OFF + BIN_BYTES)        // 190976

// Scratch: per-segment MI partials (B,C,Fp,Fa,S)
__device__ float g_partial[BB*CC*FP*FA*SSEG];

// Inner accumulate: NP p-rows per warp, 128 t-values (this copy's share of a chunk),
// 4 values + 4 bin-words per vector load. All RMW at bank==lane: conflict/race-free.
template<int NP>
__device__ __forceinline__ void run_inner(float* __restrict__ acc,
                                          const float* __restrict__ vbase,
                                          const unsigned char* __restrict__ bbase,
                                          int accWarpBase, int lane)
{
    #pragma unroll 2
    for (int jj0 = 0; jj0 < 128; jj0 += 4) {
        const float4 vals = *reinterpret_cast<const float4*>(vbase + jj0);
        const uint4  bw4  = *reinterpret_cast<const uint4*>(bbase + (size_t)jj0 * 4);
        const unsigned int bws[4] = {bw4.x, bw4.y, bw4.z, bw4.w};
        const float vs[4] = {vals.x, vals.y, vals.z, vals.w};
        #pragma unroll
        for (int e = 0; e < 4; ++e) {
            float v = vs[e];
            if (lane == 31) v = 1.0f;        // count channel (exact int in f32)
            const unsigned int bw = bws[e];
            #pragma unroll
            for (int jp = 0; jp < NP; ++jp) {
                const int bn = (bw >> (8 * jp)) & 255;
                acc[accWarpBase + (jp * NBINS + bn) * 32] += v;
            }
        }
    }
}

__global__ __launch_bounds__(NTH, 1)
void mi_partial_kernel(const float* __restrict__ pha, const float* __restrict__ amp)
{
    extern __shared__ unsigned char smem[];
    float* acc           = (float*)(smem + ACC_OFF);   // [copy][p][k][32]
    float* ampch         = (float*)(smem + AMP_OFF);   // [a][perm(tc)] stride 516
    unsigned char* binv  = smem + BIN_OFF;             // [g][c][t4][4] bin bytes

    const int bcs = blockIdx.x;           // ((b*CC + c)*SSEG + s)
    const int s   = bcs & 3;
    const int bc  = bcs >> 2;
    const int tid  = threadIdx.x;
    const int w    = tid >> 5;
    const int lane = tid & 31;

    const long phaBase = (long)bc * FP * (SSEG*TT) + (long)s * TT;
    const long ampBase = (long)bc * FA * (SSEG*TT) + (long)s * TT;

    // ---- zero accumulators + amp rows 30/31 (lane-30 reads must be benign) ----
    for (int i = tid; i < ACC_FLOATS; i += NTH) acc[i] = 0.f;
    for (int i = tid; i < AMP_FLOATS; i += NTH) ampch[i] = 0.f;
    __syncthreads();

    // ---- phase 1: bins (exact searchsorted replication), vectorized, no atomics ----
    const float PI_F = 3.14159265358979323846f;
    const float step = __fdiv_rn(2.0f * PI_F, (float)NBINS);
    const float inv_step = 1.0f / step;                 // guess only
    #pragma unroll
    for (int rep = 0; rep < FP; ++rep) {
        const int p  = rep;                  // uniform across block this rep
        const int tq = tid;                  // 512 float4 groups cover TT
        const int g  = (p < 3) ? 0 : (p < 6) ? 1 : (p < 8) ? 2 : 3;
        const int pb = (g == 0) ? 0 : (g == 1) ? 3 : (g == 2) ? 6 : 8;
        const int j  = p - pb;
        const float4 v4 = *reinterpret_cast<const float4*>(
            pha + phaBase + (long)p * (SSEG*TT) + (long)tq * 4);
        const float vv[4] = {v4.x, v4.y, v4.z, v4.w};
        #pragma unroll
        for (int e = 0; e < 4; ++e) {
            const float v = vv[e];
            int k = (int)floorf((v + PI_F) * inv_step);
            k = min(max(k, 0), NBINS - 1);
            // fixup vs exact cutoffs c[i] = fadd(-PI, fmul(i, step)); contraction-proof
            #pragma unroll
            for (int it = 0; it < 2; ++it) {
                float ck  = __fadd_rn(-PI_F, __fmul_rn((float)k,       step));
                float ck1 = __fadd_rn(-PI_F, __fmul_rn((float)(k + 1), step));
                if (k > 0 && v <= ck)                 k--;
                else if (k < NBINS - 1 && v > ck1)    k++;
            }
            binv[(((g * 4 + e) * 512) + tq) * 4 + j] = (unsigned char)k;
        }
    }
    __syncthreads();

    // ---- phase 2: chunked accumulate ----
    const int c = w & 3;                 // accumulator copy / tc residue
    const int g = w >> 2;                // p-group: {0,1,2},{3,4,5},{6,7},{8,9}
    const int pb = (g == 0) ? 0 : (g == 1) ? 3 : (g == 2) ? 6 : 8;
    const int accWarpBase = ((c * FP + pb) * NBINS) * 32 + lane;
    const float* vbase = ampch + lane * AMP_STRIDE + c * 128;

    for (int t0 = 0; t0 < TT; t0 += CHUNK) {
        // stage amp chunk: float4 gmem loads, conflict-free permuted smem writes
        for (int i = tid; i < FA * (CHUNK / 4); i += NTH) {
            const int a  = i >> 7;           // CHUNK/4 = 128
            const int tq = i & 127;
            const float4 v4 = *reinterpret_cast<const float4*>(
                amp + ampBase + (long)a * (SSEG*TT) + t0 + (long)tq * 4);
            float* row = ampch + a * AMP_STRIDE + tq;
            row[0 * 128] = v4.x;  row[1 * 128] = v4.y;
            row[2 * 128] = v4.z;  row[3 * 128] = v4.w;
        }
        __syncthreads();

        const unsigned char* bbase =
            binv + (size_t)(((g * 4 + c) * 512) + (t0 >> 2)) * 4;
        if (g < 2) run_inner<3>(acc, vbase, bbase, accWarpBase, lane);
        else       run_inner<2>(acc, vbase, bbase, accWarpBase, lane);
        __syncthreads();
    }

    // ---- phase 3: epilogue per (p,a); counts read from lane-31 channel ----
    if (tid < FP * FA) {
        const int p = tid / FA;
        const int a = tid - p * FA;
        float meanv[NBINS];
        float tot = 0.f;
        #pragma unroll
        for (int k = 0; k < NBINS; ++k) {
            float sv = 0.f, cf = 0.f;
            #pragma unroll
            for (int cpy = 0; cpy < NCOPY; ++cpy) {
                const int base = ((cpy * FP + p) * NBINS + k) * 32;
                sv += acc[base + a];
                cf += acc[base + 31];
            }
            const float m = sv / (cf + 1e-9f);
            meanv[k] = m;
            tot += m;
        }
        const float inv = 1.0f / (tot + 1e-9f);
        float ent = 0.f;
        #pragma unroll
        for (int k = 0; k < NBINS; ++k) {
            const float pr = meanv[k] * inv;
            ent += pr * logf(pr + 1e-9f);
        }
        const float L18 = 2.8903717578961645f;  // log(18)
        const float MI = (L18 + ent) / L18;
        g_partial[((long)(bc * FP + p) * FA + a) * SSEG + s] = MI;
    }
}

__global__ void mi_mean_kernel(float* __restrict__ out)
{
    int i = blockIdx.x * blockDim.x + threadIdx.x;
    if (i < BB*CC*FP*FA) {
        const float* p = g_partial + (long)i * SSEG;
        out[i] = (p[0] + p[1] + p[2] + p[3]) * 0.25f;
    }
}

extern "C" void kernel_launch(void* const* d_in, const int* in_sizes, int n_in,
                              void* d_out, int out_size)
{
    const float* pha = (const float*)d_in[0];
    const float* amp = (const float*)d_in[1];
    if (n_in >= 2 && in_sizes[0] > in_sizes[1]) {   // defensive: pha is smaller
        const float* t = pha; pha = amp; amp = t;
    }
    (void)cudaFuncSetAttribute(mi_partial_kernel,
                               cudaFuncAttributeMaxDynamicSharedMemorySize, SMEM_BYTES);
    mi_partial_kernel<<<BB*CC*SSEG, NTH, SMEM_BYTES>>>(pha, amp);
    mi_mean_kernel<<<(BB*CC*FP*FA + 255) / 256, 256>>>((float*)d_out);
}

// round 10
// speedup vs baseline: 2.1275x; 1.3860x over previous
#include <cuda_runtime.h>
#include <cuda_bf16.h>
#include <math.h>

// Problem dims
#define BB 4
#define CC 16
#define FP 10
#define FA 30
#define SSEG 4
#define TT 2048
#define NBINS 18

#define NTH 512           // 16 warps
#define CK 128            // t per chunk
#define NCHUNK 16

// SMEM layout (bytes). A: 192 rows x 128 cols bf16, row stride 272 (136 halves).
#define AST 272
#define A_OFF 0           // 192*272 = 52224
#define BH_OFF 52224      // B hi: 32 x 272
#define BL_OFF 60928      // B lo: 32 x 272
#define BIN_OFF 69632     // 10*2048 bin bytes
#define ZERO_BYTES 69632
// Epilogue overlays (all prior regions dead by then)
#define DRED_STRIDE (192*33)
#define DFIN_OFF 76032    // 3*192*33*4 = 76032
#define SMEM_BYTES 101376 // 76032 + 192*33*4

__device__ float g_partial[BB*CC*FP*FA*SSEG];

__device__ __forceinline__ unsigned smem_u32(const void* p) {
    unsigned r;
    asm("{ .reg .u64 t; cvta.to.shared.u64 t, %1; cvt.u32.u64 %0, t; }"
        : "=r"(r) : "l"(p));
    return r;
}
__device__ __forceinline__ void ldsm_x4(unsigned addr, unsigned& r0, unsigned& r1,
                                        unsigned& r2, unsigned& r3) {
    asm volatile("ldmatrix.sync.aligned.m8n8.x4.shared.b16 {%0,%1,%2,%3}, [%4];"
                 : "=r"(r0), "=r"(r1), "=r"(r2), "=r"(r3) : "r"(addr));
}
__device__ __forceinline__ void mma16816(float* c, unsigned a0, unsigned a1,
                                         unsigned a2, unsigned a3,
                                         unsigned b0, unsigned b1) {
    asm volatile("mma.sync.aligned.m16n8k16.row.col.f32.bf16.bf16.f32 "
                 "{%0,%1,%2,%3}, {%4,%5,%6,%7}, {%8,%9}, {%0,%1,%2,%3};"
                 : "+f"(c[0]), "+f"(c[1]), "+f"(c[2]), "+f"(c[3])
                 : "r"(a0), "r"(a1), "r"(a2), "r"(a3), "r"(b0), "r"(b1));
}

__device__ __forceinline__ void storeB_item(unsigned char* smem, float4 v, int item) {
    const int a = item >> 5, tq = item & 31;
    __nv_bfloat16 h0 = __float2bfloat16(v.x), h1 = __float2bfloat16(v.y);
    __nv_bfloat16 h2 = __float2bfloat16(v.z), h3 = __float2bfloat16(v.w);
    __nv_bfloat16 l0 = __float2bfloat16(v.x - __bfloat162float(h0));
    __nv_bfloat16 l1 = __float2bfloat16(v.y - __bfloat162float(h1));
    __nv_bfloat16 l2 = __float2bfloat16(v.z - __bfloat162float(h2));
    __nv_bfloat16 l3 = __float2bfloat16(v.w - __bfloat162float(h3));
    uint2 hi = make_uint2(
        (unsigned)__bfloat16_as_ushort(h0) | ((unsigned)__bfloat16_as_ushort(h1) << 16),
        (unsigned)__bfloat16_as_ushort(h2) | ((unsigned)__bfloat16_as_ushort(h3) << 16));
    uint2 lo = make_uint2(
        (unsigned)__bfloat16_as_ushort(l0) | ((unsigned)__bfloat16_as_ushort(l1) << 16),
        (unsigned)__bfloat16_as_ushort(l2) | ((unsigned)__bfloat16_as_ushort(l3) << 16));
    *(uint2*)(smem + BH_OFF + a * AST + tq * 8) = hi;
    *(uint2*)(smem + BL_OFF + a * AST + tq * 8) = lo;
}

__global__ __launch_bounds__(NTH, 1)
void mi_mma_kernel(const float* __restrict__ pha, const float* __restrict__ amp)
{
    extern __shared__ __align__(16) unsigned char smem[];
    const unsigned sb = smem_u32(smem);
    const int tid = threadIdx.x, wid = tid >> 5, lane = tid & 31;
    const int bcs = blockIdx.x, s = bcs & 3, bc = bcs >> 2;
    const long phaBase = (long)bc * FP * (SSEG*TT) + (long)s * TT;
    const long ampBase = (long)bc * FA * (SSEG*TT) + (long)s * TT;
    unsigned char* binp = smem + BIN_OFF;

    // zero A + B regions
    for (int i = tid; i < ZERO_BYTES / 16; i += NTH)
        ((uint4*)smem)[i] = make_uint4(0, 0, 0, 0);

    // ---- phase 1: exact searchsorted bins -> binp[p*2048 + t] ----
    const float PI_F = 3.14159265358979323846f;
    const float step = __fdiv_rn(2.0f * PI_F, (float)NBINS);
    const float inv_step = 1.0f / step;
    #pragma unroll
    for (int p = 0; p < FP; ++p) {
        const float4 v4 = *(const float4*)(pha + phaBase + (long)p * (SSEG*TT) + (long)tid * 4);
        const float vv[4] = {v4.x, v4.y, v4.z, v4.w};
        uchar4 kb;
        unsigned char* kk = (unsigned char*)&kb;
        #pragma unroll
        for (int e = 0; e < 4; ++e) {
            const float v = vv[e];
            int k = (int)floorf((v + PI_F) * inv_step);
            k = min(max(k, 0), NBINS - 1);
            #pragma unroll
            for (int it = 0; it < 2; ++it) {
                float ck  = __fadd_rn(-PI_F, __fmul_rn((float)k,       step));
                float ck1 = __fadd_rn(-PI_F, __fmul_rn((float)(k + 1), step));
                if (k > 0 && v <= ck)              k--;
                else if (k < NBINS - 1 && v > ck1) k++;
            }
            kk[e] = (unsigned char)k;
        }
        *(uchar4*)(binp + p * TT + tid * 4) = kb;
    }
    __syncthreads();

    // ones row (a=30) of B hi: the counts channel
    if (tid < 128)
        *(unsigned short*)(smem + BH_OFF + 30 * AST + tid * 2) = 0x3F80;

    // ---- build chunk 0 ----
    const int pS = tid >> 5, cS0 = (tid & 31) * 4;   // ones scatter mapping
    {
        if (tid < 320) {
            uchar4 nb = *(const uchar4*)(binp + pS * TT + cS0);
            const unsigned char* nk = (const unsigned char*)&nb;
            #pragma unroll
            for (int e = 0; e < 4; ++e)
                *(unsigned short*)(smem + (unsigned)(pS * NBINS + nk[e]) * AST +
                                   (cS0 + e) * 2) = 0x3F80;
        }
        const int a0i = tid >> 5, tq0 = tid & 31;
        float4 f0 = *(const float4*)(amp + ampBase + (long)a0i * (SSEG*TT) + tq0 * 4);
        storeB_item(smem, f0, tid);
        if (tid < 448) {
            const int a1i = (tid + 512) >> 5, tq1 = (tid + 512) & 31;
            float4 f1 = *(const float4*)(amp + ampBase + (long)a1i * (SSEG*TT) + tq1 * 4);
            storeB_item(smem, f1, tid + 512);
        }
    }
    __syncthreads();

    // ---- MMA mainloop: K-split 4 x M-split 4 ----
    const int kg = wid & 3, mg = wid >> 2;
    const unsigned aAddrBase = sb + A_OFF + (unsigned)(mg * 48 + (lane & 15)) * AST +
                               (((lane >> 4) & 1) << 4);             // +16B if k-half hi
    const unsigned nrow  = (lane & 7) + (((lane >> 4) & 1) << 3);
    const unsigned kadd2 = (((lane >> 3) & 1) << 4);                 // +16B if k-half hi
    float acc[3][4][4];
    #pragma unroll
    for (int mt = 0; mt < 3; ++mt)
        #pragma unroll
        for (int nt = 0; nt < 4; ++nt)
            #pragma unroll
            for (int e = 0; e < 4; ++e) acc[mt][nt][e] = 0.f;

    float4 pf0, pf1;
    for (int i = 0; i < NCHUNK; ++i) {
        const int t0 = i * CK;
        if (i + 1 < NCHUNK) {  // prefetch next amp chunk (lands during MMA)
            const int a0i = tid >> 5, tq0 = tid & 31;
            pf0 = *(const float4*)(amp + ampBase + (long)a0i * (SSEG*TT) + t0 + CK + tq0 * 4);
            if (tid < 448) {
                const int a1i = (tid + 512) >> 5, tq1 = (tid + 512) & 31;
                pf1 = *(const float4*)(amp + ampBase + (long)a1i * (SSEG*TT) + t0 + CK + tq1 * 4);
            }
        }
        #pragma unroll
        for (int ks = 0; ks < 2; ++ks) {
            const int k0 = kg * 32 + ks * 16;
            unsigned a0[3], a1[3], a2[3], a3[3];
            #pragma unroll
            for (int mt = 0; mt < 3; ++mt)
                ldsm_x4(aAddrBase + mt * 16 * AST + k0 * 2, a0[mt], a1[mt], a2[mt], a3[mt]);
            unsigned bh[8], bl[8];
            #pragma unroll
            for (int np = 0; np < 2; ++np) {
                const unsigned bOff = (unsigned)(np * 16 + nrow) * AST + k0 * 2 + kadd2;
                ldsm_x4(sb + BH_OFF + bOff, bh[np*4], bh[np*4+1], bh[np*4+2], bh[np*4+3]);
                ldsm_x4(sb + BL_OFF + bOff, bl[np*4], bl[np*4+1], bl[np*4+2], bl[np*4+3]);
            }
            #pragma unroll
            for (int mt = 0; mt < 3; ++mt)
                #pragma unroll
                for (int nt = 0; nt < 4; ++nt) {
                    const int bi = (nt >> 1) * 4 + (nt & 1) * 2;
                    mma16816(acc[mt][nt], a0[mt], a1[mt], a2[mt], a3[mt], bh[bi], bh[bi+1]);
                    mma16816(acc[mt][nt], a0[mt], a1[mt], a2[mt], a3[mt], bl[bi], bl[bi+1]);
                }
        }
        __syncthreads();
        if (i + 1 < NCHUNK) {
            if (tid < 320) {   // clear old ones, set new ones (same thread, ordered)
                uchar4 ob = *(const uchar4*)(binp + pS * TT + t0 + cS0);
                const unsigned char* ok = (const unsigned char*)&ob;
                #pragma unroll
                for (int e = 0; e < 4; ++e)
                    *(unsigned short*)(smem + (unsigned)(pS * NBINS + ok[e]) * AST +
                                       (cS0 + e) * 2) = 0;
                uchar4 nb = *(const uchar4*)(binp + pS * TT + t0 + CK + cS0);
                const unsigned char* nk = (const unsigned char*)&nb;
                #pragma unroll
                for (int e = 0; e < 4; ++e)
                    *(unsigned short*)(smem + (unsigned)(pS * NBINS + nk[e]) * AST +
                                       (cS0 + e) * 2) = 0x3F80;
            }
            storeB_item(smem, pf0, tid);
            if (tid < 448) storeB_item(smem, pf1, tid + 512);
            __syncthreads();
        }
    }

    // ---- K-split reduction (deterministic, stride-33 conflict-free) ----
    const int rrow = lane >> 2, rcol = (lane & 3) * 2;
    if (kg) {
        float* dst = (float*)smem + (unsigned)(kg - 1) * DRED_STRIDE;
        #pragma unroll
        for (int mt = 0; mt < 3; ++mt)
            #pragma unroll
            for (int nt = 0; nt < 4; ++nt) {
                const int row = mg * 48 + mt * 16 + rrow, col = nt * 8 + rcol;
                dst[row * 33 + col]           = acc[mt][nt][0];
                dst[row * 33 + col + 1]       = acc[mt][nt][1];
                dst[(row + 8) * 33 + col]     = acc[mt][nt][2];
                dst[(row + 8) * 33 + col + 1] = acc[mt][nt][3];
            }
    }
    __syncthreads();
    if (!kg) {
        float* Dfin = (float*)(smem + DFIN_OFF);
        const float* dr = (const float*)smem;
        #pragma unroll
        for (int mt = 0; mt < 3; ++mt)
            #pragma unroll
            for (int nt = 0; nt < 4; ++nt) {
                const int row = mg * 48 + mt * 16 + rrow, col = nt * 8 + rcol;
                const int i0 = row * 33 + col, i2 = (row + 8) * 33 + col;
                Dfin[i0]     = acc[mt][nt][0] + dr[i0] + dr[DRED_STRIDE + i0] + dr[2*DRED_STRIDE + i0];
                Dfin[i0 + 1] = acc[mt][nt][1] + dr[i0+1] + dr[DRED_STRIDE + i0+1] + dr[2*DRED_STRIDE + i0+1];
                Dfin[i2]     = acc[mt][nt][2] + dr[i2] + dr[DRED_STRIDE + i2] + dr[2*DRED_STRIDE + i2];
                Dfin[i2 + 1] = acc[mt][nt][3] + dr[i2+1] + dr[DRED_STRIDE + i2+1] + dr[2*DRED_STRIDE + i2+1];
            }
    }
    __syncthreads();

    // ---- epilogue per (p,a); counts in col 30 ----
    if (tid < FP * FA) {
        const float* Dfin = (const float*)(smem + DFIN_OFF);
        const int p = tid / FA;
        const int a = tid - p * FA;
        float meanv[NBINS];
        float tot = 0.f;
        #pragma unroll
        for (int k = 0; k < NBINS; ++k) {
            const float sv = Dfin[(p * NBINS + k) * 33 + a];
            const float cf = Dfin[(p * NBINS + k) * 33 + 30];
            const float m = sv / (cf + 1e-9f);
            meanv[k] = m;
            tot += m;
        }
        const float inv = 1.0f / (tot + 1e-9f);
        float ent = 0.f;
        #pragma unroll
        for (int k = 0; k < NBINS; ++k) {
            const float pr = meanv[k] * inv;
            ent += pr * logf(pr + 1e-9f);
        }
        const float L18 = 2.8903717578961645f;  // log(18)
        g_partial[((long)(bc * FP + p) * FA + a) * SSEG + s] = (L18 + ent) / L18;
    }
}

__global__ void mi_mean_kernel(float* __restrict__ out)
{
    int i = blockIdx.x * blockDim.x + threadIdx.x;
    if (i < BB*CC*FP*FA) {
        const float* p = g_partial + (long)i * SSEG;
        out[i] = (p[0] + p[1] + p[2] + p[3]) * 0.25f;
    }
}

extern "C" void kernel_launch(void* const* d_in, const int* in_sizes, int n_in,
                              void* d_out, int out_size)
{
    const float* pha = (const float*)d_in[0];
    const float* amp = (const float*)d_in[1];
    if (n_in >= 2 && in_sizes[0] > in_sizes[1]) {   // defensive: pha is smaller
        const float* t = pha; pha = amp; amp = t;
    }
    (void)cudaFuncSetAttribute(mi_mma_kernel,
                               cudaFuncAttributeMaxDynamicSharedMemorySize, SMEM_BYTES);
    mi_mma_kernel<<<BB*CC*SSEG, NTH, SMEM_BYTES>>>(pha, amp);
    mi_mean_kernel<<<(BB*CC*FP*FA + 255) / 256, 256>>>((float*)d_out);
}

// round 12
// speedup vs baseline: 2.8805x; 1.3540x over previous
#include <cuda_runtime.h>
#include <cuda_bf16.h>
#include <cuda_fp16.h>
#include <math.h>

// Problem dims
#define BB 4
#define CC 16
#define FP 10
#define FA 30
#define SSEG 4
#define TT 2048
#define NBINS 18

#define NTH 512           // 16 warps
#define CK 128            // t per chunk
#define NCHUNK 16

// SMEM layout (bytes). A: 192 rows x 128 cols fp16, row stride 272 (136 halves).
#define AST 272
#define A_OFF 0           // 192*272 = 52224
#define BH_OFF 52224      // B: 32 x 272 fp16
#define BIN_OFF 60928     // 10*2048 bin bytes (ends 81408)
#define ZERO_BYTES 60928
// Epilogue overlays (all prior regions dead by then)
#define DRED_STRIDE (192*33)
#define DFIN_OFF 76032    // 3*192*33*4 = 76032
#define SMEM_BYTES 101376 // 76032 + 192*33*4

#define ONE_F16 0x3C00

__device__ float g_partial[BB*CC*FP*FA*SSEG];

__device__ __forceinline__ unsigned smem_u32(const void* p) {
    unsigned r;
    asm("{ .reg .u64 t; cvta.to.shared.u64 t, %1; cvt.u32.u64 %0, t; }"
        : "=r"(r) : "l"(p));
    return r;
}
__device__ __forceinline__ void ldsm_x4(unsigned addr, unsigned& r0, unsigned& r1,
                                        unsigned& r2, unsigned& r3) {
    asm volatile("ldmatrix.sync.aligned.m8n8.x4.shared.b16 {%0,%1,%2,%3}, [%4];"
                 : "=r"(r0), "=r"(r1), "=r"(r2), "=r"(r3) : "r"(addr));
}
__device__ __forceinline__ void mma16816(float* c, unsigned a0, unsigned a1,
                                         unsigned a2, unsigned a3,
                                         unsigned b0, unsigned b1) {
    asm volatile("mma.sync.aligned.m16n8k16.row.col.f32.f16.f16.f32 "
                 "{%0,%1,%2,%3}, {%4,%5,%6,%7}, {%8,%9}, {%0,%1,%2,%3};"
                 : "+f"(c[0]), "+f"(c[1]), "+f"(c[2]), "+f"(c[3])
                 : "r"(a0), "r"(a1), "r"(a2), "r"(a3), "r"(b0), "r"(b1));
}

__device__ __forceinline__ void storeB_item(unsigned char* smem, float4 v, int item) {
    const int a = item >> 5, tq = item & 31;
    __half2 p01 = __floats2half2_rn(v.x, v.y);
    __half2 p23 = __floats2half2_rn(v.z, v.w);
    uint2 w = make_uint2(*(const unsigned*)&p01, *(const unsigned*)&p23);
    *(uint2*)(smem + BH_OFF + a * AST + tq * 8) = w;
}

__global__ __launch_bounds__(NTH, 1)
void mi_mma_kernel(const float* __restrict__ pha, const float* __restrict__ amp)
{
    extern __shared__ __align__(16) unsigned char smem[];
    const unsigned sb = smem_u32(smem);
    const int tid = threadIdx.x, wid = tid >> 5, lane = tid & 31;
    const int bcs = blockIdx.x, s = bcs & 3, bc = bcs >> 2;
    const long phaBase = (long)bc * FP * (SSEG*TT) + (long)s * TT;
    const long ampBase = (long)bc * FA * (SSEG*TT) + (long)s * TT;
    unsigned char* binp = smem + BIN_OFF;

    // zero A + B regions
    for (int i = tid; i < ZERO_BYTES / 16; i += NTH)
        ((uint4*)smem)[i] = make_uint4(0, 0, 0, 0);

    // ---- phase 1: exact searchsorted bins -> binp[p*2048 + t] ----
    const float PI_F = 3.14159265358979323846f;
    const float step = __fdiv_rn(2.0f * PI_F, (float)NBINS);
    const float inv_step = 1.0f / step;
    #pragma unroll
    for (int p = 0; p < FP; ++p) {
        const float4 v4 = *(const float4*)(pha + phaBase + (long)p * (SSEG*TT) + (long)tid * 4);
        const float vv[4] = {v4.x, v4.y, v4.z, v4.w};
        uchar4 kb;
        unsigned char* kk = (unsigned char*)&kb;
        #pragma unroll
        for (int e = 0; e < 4; ++e) {
            const float v = vv[e];
            int k = (int)floorf((v + PI_F) * inv_step);
            k = min(max(k, 0), NBINS - 1);
            #pragma unroll
            for (int it = 0; it < 2; ++it) {
                float ck  = __fadd_rn(-PI_F, __fmul_rn((float)k,       step));
                float ck1 = __fadd_rn(-PI_F, __fmul_rn((float)(k + 1), step));
                if (k > 0 && v <= ck)              k--;
                else if (k < NBINS - 1 && v > ck1) k++;
            }
            kk[e] = (unsigned char)k;
        }
        *(uchar4*)(binp + p * TT + tid * 4) = kb;
    }
    __syncthreads();

    // ones row (a=30) of B: the counts channel
    if (tid < 128)
        *(unsigned short*)(smem + BH_OFF + 30 * AST + tid * 2) = ONE_F16;

    // ---- build chunk 0 ----
    const int pS = tid >> 5, cS0 = (tid & 31) * 4;   // ones scatter mapping
    {
        if (tid < 320) {
            uchar4 nb = *(const uchar4*)(binp + pS * TT + cS0);
            const unsigned char* nk = (const unsigned char*)&nb;
            #pragma unroll
            for (int e = 0; e < 4; ++e)
                *(unsigned short*)(smem + (unsigned)(pS * NBINS + nk[e]) * AST +
                                   (cS0 + e) * 2) = ONE_F16;
        }
        const int a0i = tid >> 5, tq0 = tid & 31;
        float4 f0 = *(const float4*)(amp + ampBase + (long)a0i * (SSEG*TT) + tq0 * 4);
        storeB_item(smem, f0, tid);
        if (tid < 448) {
            const int a1i = (tid + 512) >> 5, tq1 = (tid + 512) & 31;
            float4 f1 = *(const float4*)(amp + ampBase + (long)a1i * (SSEG*TT) + tq1 * 4);
            storeB_item(smem, f1, tid + 512);
        }
    }
    __syncthreads();

    // ---- MMA mainloop: K-split 4 x M-split 4 ----
    const int kg = wid & 3, mg = wid >> 2;
    const unsigned aAddrBase = sb + A_OFF + (unsigned)(mg * 48 + (lane & 15)) * AST +
                               (((lane >> 4) & 1) << 4);             // +16B if k-half hi
    const unsigned nrow  = (lane & 7) + (((lane >> 4) & 1) << 3);
    const unsigned kadd2 = (((lane >> 3) & 1) << 4);                 // +16B if k-half hi
    float acc[3][4][4];
    #pragma unroll
    for (int mt = 0; mt < 3; ++mt)
        #pragma unroll
        for (int nt = 0; nt < 4; ++nt)
            #pragma unroll
            for (int e = 0; e < 4; ++e) acc[mt][nt][e] = 0.f;

    float4 pf0, pf1;
    for (int i = 0; i < NCHUNK; ++i) {
        const int t0 = i * CK;
        if (i + 1 < NCHUNK) {  // prefetch next amp chunk (lands during MMA)
            const int a0i = tid >> 5, tq0 = tid & 31;
            pf0 = *(const float4*)(amp + ampBase + (long)a0i * (SSEG*TT) + t0 + CK + tq0 * 4);
            if (tid < 448) {
                const int a1i = (tid + 512) >> 5, tq1 = (tid + 512) & 31;
                pf1 = *(const float4*)(amp + ampBase + (long)a1i * (SSEG*TT) + t0 + CK + tq1 * 4);
            }
        }
        #pragma unroll
        for (int ks = 0; ks < 2; ++ks) {
            const int k0 = kg * 32 + ks * 16;
            unsigned a0[3], a1[3], a2[3], a3[3];
            #pragma unroll
            for (int mt = 0; mt < 3; ++mt)
                ldsm_x4(aAddrBase + mt * 16 * AST + k0 * 2, a0[mt], a1[mt], a2[mt], a3[mt]);
            unsigned bh[8];
            #pragma unroll
            for (int np = 0; np < 2; ++np) {
                const unsigned bOff = (unsigned)(np * 16 + nrow) * AST + k0 * 2 + kadd2;
                ldsm_x4(sb + BH_OFF + bOff, bh[np*4], bh[np*4+1], bh[np*4+2], bh[np*4+3]);
            }
            #pragma unroll
            for (int mt = 0; mt < 3; ++mt)
                #pragma unroll
                for (int nt = 0; nt < 4; ++nt) {
                    const int bi = (nt >> 1) * 4 + (nt & 1) * 2;
                    mma16816(acc[mt][nt], a0[mt], a1[mt], a2[mt], a3[mt], bh[bi], bh[bi+1]);
                }
        }
        __syncthreads();
        if (i + 1 < NCHUNK) {
            if (tid < 320) {   // clear old ones, set new ones (same thread, ordered)
                uchar4 ob = *(const uchar4*)(binp + pS * TT + t0 + cS0);
                const unsigned char* ok = (const unsigned char*)&ob;
                #pragma unroll
                for (int e = 0; e < 4; ++e)
                    *(unsigned short*)(smem + (unsigned)(pS * NBINS + ok[e]) * AST +
                                       (cS0 + e) * 2) = 0;
                uchar4 nb = *(const uchar4*)(binp + pS * TT + t0 + CK + cS0);
                const unsigned char* nk = (const unsigned char*)&nb;
                #pragma unroll
                for (int e = 0; e < 4; ++e)
                    *(unsigned short*)(smem + (unsigned)(pS * NBINS + nk[e]) * AST +
                                       (cS0 + e) * 2) = ONE_F16;
            }
            storeB_item(smem, pf0, tid);
            if (tid < 448) storeB_item(smem, pf1, tid + 512);
            __syncthreads();
        }
    }

    // ---- K-split reduction (deterministic, stride-33 conflict-free) ----
    const int rrow = lane >> 2, rcol = (lane & 3) * 2;
    if (kg) {
        float* dst = (float*)smem + (unsigned)(kg - 1) * DRED_STRIDE;
        #pragma unroll
        for (int mt = 0; mt < 3; ++mt)
            #pragma unroll
            for (int nt = 0; nt < 4; ++nt) {
                const int row = mg * 48 + mt * 16 + rrow, col = nt * 8 + rcol;
                dst[row * 33 + col]           = acc[mt][nt][0];
                dst[row * 33 + col + 1]       = acc[mt][nt][1];
                dst[(row + 8) * 33 + col]     = acc[mt][nt][2];
                dst[(row + 8) * 33 + col + 1] = acc[mt][nt][3];
            }
    }
    __syncthreads();
    if (!kg) {
        float* Dfin = (float*)(smem + DFIN_OFF);
        const float* dr = (const float*)smem;
        #pragma unroll
        for (int mt = 0; mt < 3; ++mt)
            #pragma unroll
            for (int nt = 0; nt < 4; ++nt) {
                const int row = mg * 48 + mt * 16 + rrow, col = nt * 8 + rcol;
                const int i0 = row * 33 + col, i2 = (row + 8) * 33 + col;
                Dfin[i0]     = acc[mt][nt][0] + dr[i0] + dr[DRED_STRIDE + i0] + dr[2*DRED_STRIDE + i0];
                Dfin[i0 + 1] = acc[mt][nt][1] + dr[i0+1] + dr[DRED_STRIDE + i0+1] + dr[2*DRED_STRIDE + i0+1];
                Dfin[i2]     = acc[mt][nt][2] + dr[i2] + dr[DRED_STRIDE + i2] + dr[2*DRED_STRIDE + i2];
                Dfin[i2 + 1] = acc[mt][nt][3] + dr[i2+1] + dr[DRED_STRIDE + i2+1] + dr[2*DRED_STRIDE + i2+1];
            }
    }
    __syncthreads();

    // ---- epilogue per (p,a); counts in col 30 ----
    if (tid < FP * FA) {
        const float* Dfin = (const float*)(smem + DFIN_OFF);
        const int p = tid / FA;
        const int a = tid - p * FA;
        float meanv[NBINS];
        float tot = 0.f;
        #pragma unroll
        for (int k = 0; k < NBINS; ++k) {
            const float sv = Dfin[(p * NBINS + k) * 33 + a];
            const float cf = Dfin[(p * NBINS + k) * 33 + 30];
            const float m = sv / (cf + 1e-9f);
            meanv[k] = m;
            tot += m;
        }
        const float inv = 1.0f / (tot + 1e-9f);
        float ent = 0.f;
        #pragma unroll
        for (int k = 0; k < NBINS; ++k) {
            const float pr = meanv[k] * inv;
            ent += pr * logf(pr + 1e-9f);
        }
        const float L18 = 2.8903717578961645f;  // log(18)
        g_partial[((long)(bc * FP + p) * FA + a) * SSEG + s] = (L18 + ent) / L18;
    }
}

__global__ void mi_mean_kernel(float* __restrict__ out)
{
    int i = blockIdx.x * blockDim.x + threadIdx.x;
    if (i < BB*CC*FP*FA) {
        const float* p = g_partial + (long)i * SSEG;
        out[i] = (p[0] + p[1] + p[2] + p[3]) * 0.25f;
    }
}

extern "C" void kernel_launch(void* const* d_in, const int* in_sizes, int n_in,
                              void* d_out, int out_size)
{
    const float* pha = (const float*)d_in[0];
    const float* amp = (const float*)d_in[1];
    if (n_in >= 2 && in_sizes[0] > in_sizes[1]) {   // defensive: pha is smaller
        const float* t = pha; pha = amp; amp = t;
    }
    (void)cudaFuncSetAttribute(mi_mma_kernel,
                               cudaFuncAttributeMaxDynamicSharedMemorySize, SMEM_BYTES);
    mi_mma_kernel<<<BB*CC*SSEG, NTH, SMEM_BYTES>>>(pha, amp);
    mi_mean_kernel<<<(BB*CC*FP*FA + 255) / 256, 256>>>((float*)d_out);
}

// round 14
// speedup vs baseline: 2.9111x; 1.0106x over previous
#include <cuda_runtime.h>
#include <cuda_bf16.h>
#include <cuda_fp16.h>
#include <math.h>

// Problem dims
#define BB 4
#define CC 16
#define FP 10
#define FA 30
#define SSEG 4
#define TT 2048
#define NBINS 18

#define NTH 512           // 16 warps
#define CK 128            // t per chunk
#define NCHUNK 16

// SMEM layout (bytes). A: 192 rows x 128 cols fp16, row stride 272 B. Two buffers.
#define AST 272
#define ABUF 52224        // 192*272
#define B_OFF 104448      // two B buffers: 32 x 272 fp16 each
#define BBUF 8704
#define BIN_OFF 121856    // 10*2048 bin bytes
#define ZERO_BYTES 121856
// Epilogue overlays A region (dead by then)
#define DRED_STRIDE (192*33)
#define DFIN_OFF 76032    // 3*192*33*4
#define SMEM_BYTES 142336

#define ONE_F16 0x3C00

__device__ float g_partial[BB*CC*FP*FA*SSEG];

__device__ __forceinline__ unsigned smem_u32(const void* p) {
    unsigned r;
    asm("{ .reg .u64 t; cvta.to.shared.u64 t, %1; cvt.u32.u64 %0, t; }"
        : "=r"(r) : "l"(p));
    return r;
}
__device__ __forceinline__ void ldsm_x4(unsigned addr, unsigned& r0, unsigned& r1,
                                        unsigned& r2, unsigned& r3) {
    asm volatile("ldmatrix.sync.aligned.m8n8.x4.shared.b16 {%0,%1,%2,%3}, [%4];"
                 : "=r"(r0), "=r"(r1), "=r"(r2), "=r"(r3) : "r"(addr));
}
__device__ __forceinline__ void mma16816(float* c, unsigned a0, unsigned a1,
                                         unsigned a2, unsigned a3,
                                         unsigned b0, unsigned b1) {
    asm volatile("mma.sync.aligned.m16n8k16.row.col.f32.f16.f16.f32 "
                 "{%0,%1,%2,%3}, {%4,%5,%6,%7}, {%8,%9}, {%0,%1,%2,%3};"
                 : "+f"(c[0]), "+f"(c[1]), "+f"(c[2]), "+f"(c[3])
                 : "r"(a0), "r"(a1), "r"(a2), "r"(a3), "r"(b0), "r"(b1));
}

__device__ __forceinline__ void storeB_item(unsigned char* smem, float4 v, int item,
                                            int buf) {
    const int a = item >> 5, tq = item & 31;
    __half2 p01 = __floats2half2_rn(v.x, v.y);
    __half2 p23 = __floats2half2_rn(v.z, v.w);
    uint2 w = make_uint2(*(const unsigned*)&p01, *(const unsigned*)&p23);
    *(uint2*)(smem + B_OFF + buf * BBUF + a * AST + tq * 8) = w;
}

__global__ __launch_bounds__(NTH, 1)
void mi_mma_kernel(const float* __restrict__ pha, const float* __restrict__ amp)
{
    extern __shared__ __align__(16) unsigned char smem[];
    const unsigned sb = smem_u32(smem);
    const int tid = threadIdx.x, wid = tid >> 5, lane = tid & 31;
    const int bcs = blockIdx.x, s = bcs & 3, bc = bcs >> 2;
    const long phaBase = (long)bc * FP * (SSEG*TT) + (long)s * TT;
    const long ampBase = (long)bc * FA * (SSEG*TT) + (long)s * TT;
    unsigned char* binp = smem + BIN_OFF;

    // zero both A buffers + both B buffers
    for (int i = tid; i < ZERO_BYTES / 16; i += NTH)
        ((uint4*)smem)[i] = make_uint4(0, 0, 0, 0);

    // ---- phase 1: exact searchsorted bins -> binp[p*2048 + t] ----
    const float PI_F = 3.14159265358979323846f;
    const float step = __fdiv_rn(2.0f * PI_F, (float)NBINS);
    const float inv_step = 1.0f / step;
    #pragma unroll
    for (int p = 0; p < FP; ++p) {
        const float4 v4 = *(const float4*)(pha + phaBase + (long)p * (SSEG*TT) + (long)tid * 4);
        const float vv[4] = {v4.x, v4.y, v4.z, v4.w};
        uchar4 kb;
        unsigned char* kk = (unsigned char*)&kb;
        #pragma unroll
        for (int e = 0; e < 4; ++e) {
            const float v = vv[e];
            int k = (int)floorf((v + PI_F) * inv_step);
            k = min(max(k, 0), NBINS - 1);
            #pragma unroll
            for (int it = 0; it < 2; ++it) {
                float ck  = __fadd_rn(-PI_F, __fmul_rn((float)k,       step));
                float ck1 = __fadd_rn(-PI_F, __fmul_rn((float)(k + 1), step));
                if (k > 0 && v <= ck)              k--;
                else if (k < NBINS - 1 && v > ck1) k++;
            }
            kk[e] = (unsigned char)k;
        }
        *(uchar4*)(binp + p * TT + tid * 4) = kb;
    }
    __syncthreads();

    // ones row (a=30) of both B buffers: the counts channel (never overwritten)
    if (tid < 256) {
        const int buf = tid >> 7, c = tid & 127;
        *(unsigned short*)(smem + B_OFF + buf * BBUF + 30 * AST + c * 2) = ONE_F16;
    }

    // ---- build chunk 0 into buffer 0 (set-only; buffer pre-zeroed) ----
    const int pS = tid >> 5, cS0 = (tid & 31) * 4;   // ones scatter mapping
    {
        if (tid < 320) {
            uchar4 nb = *(const uchar4*)(binp + pS * TT + cS0);
            const unsigned char* nk = (const unsigned char*)&nb;
            #pragma unroll
            for (int e = 0; e < 4; ++e)
                *(unsigned short*)(smem + (unsigned)(pS * NBINS + nk[e]) * AST +
                                   (cS0 + e) * 2) = ONE_F16;
        }
        const int a0i = tid >> 5, tq0 = tid & 31;
        float4 f0 = *(const float4*)(amp + ampBase + (long)a0i * (SSEG*TT) + tq0 * 4);
        storeB_item(smem, f0, tid, 0);
        if (tid < 448) {
            const int a1i = (tid + 512) >> 5, tq1 = (tid + 512) & 31;
            float4 f1 = *(const float4*)(amp + ampBase + (long)a1i * (SSEG*TT) + tq1 * 4);
            storeB_item(smem, f1, tid + 512, 0);
        }
    }
    __syncthreads();

    // ---- MMA mainloop: K-split 4 x M-split 4, double-buffered, one sync/chunk ----
    const int kg = wid & 3, mg = wid >> 2;
    const unsigned aAddrOff = (unsigned)(mg * 48 + (lane & 15)) * AST +
                              (((lane >> 4) & 1) << 4);              // +16B if k-half hi
    const unsigned nrow  = (lane & 7) + (((lane >> 4) & 1) << 3);
    const unsigned kadd2 = (((lane >> 3) & 1) << 4);                 // +16B if k-half hi
    float acc[3][4][4];
    #pragma unroll
    for (int mt = 0; mt < 3; ++mt)
        #pragma unroll
        for (int nt = 0; nt < 4; ++nt)
            #pragma unroll
            for (int e = 0; e < 4; ++e) acc[mt][nt][e] = 0.f;

    for (int i = 0; i < NCHUNK; ++i) {
        const int buf = i & 1, nbuf = buf ^ 1;
        const int t0 = i * CK;
        float4 pf0, pf1;
        if (i + 1 < NCHUNK) {  // prefetch next amp chunk (lands during MMA)
            const int a0i = tid >> 5, tq0 = tid & 31;
            pf0 = *(const float4*)(amp + ampBase + (long)a0i * (SSEG*TT) + t0 + CK + tq0 * 4);
            if (tid < 448) {
                const int a1i = (tid + 512) >> 5, tq1 = (tid + 512) & 31;
                pf1 = *(const float4*)(amp + ampBase + (long)a1i * (SSEG*TT) + t0 + CK + tq1 * 4);
            }
        }
        // MMA on buf
        const unsigned aAddrBase = sb + (unsigned)buf * ABUF + aAddrOff;
        const unsigned bBase = sb + B_OFF + (unsigned)buf * BBUF;
        #pragma unroll
        for (int ks = 0; ks < 2; ++ks) {
            const int k0 = kg * 32 + ks * 16;
            unsigned a0[3], a1[3], a2[3], a3[3];
            #pragma unroll
            for (int mt = 0; mt < 3; ++mt)
                ldsm_x4(aAddrBase + mt * 16 * AST + k0 * 2, a0[mt], a1[mt], a2[mt], a3[mt]);
            unsigned bh[8];
            #pragma unroll
            for (int np = 0; np < 2; ++np) {
                const unsigned bOff = (unsigned)(np * 16 + nrow) * AST + k0 * 2 + kadd2;
                ldsm_x4(bBase + bOff, bh[np*4], bh[np*4+1], bh[np*4+2], bh[np*4+3]);
            }
            #pragma unroll
            for (int mt = 0; mt < 3; ++mt)
                #pragma unroll
                for (int nt = 0; nt < 4; ++nt) {
                    const int bi = (nt >> 1) * 4 + (nt & 1) * 2;
                    mma16816(acc[mt][nt], a0[mt], a1[mt], a2[mt], a3[mt], bh[bi], bh[bi+1]);
                }
        }
        // build chunk i+1 into nbuf (overlaps MMA issue; no extra sync needed)
        if (i + 1 < NCHUNK) {
            if (tid < 320) {
                unsigned char* an = smem + (unsigned)nbuf * ABUF;
                if (i >= 1) {   // clear chunk i-1's ones (last written into nbuf)
                    uchar4 ob = *(const uchar4*)(binp + pS * TT + (t0 - CK) + cS0);
                    const unsigned char* ok = (const unsigned char*)&ob;
                    #pragma unroll
                    for (int e = 0; e < 4; ++e)
                        *(unsigned short*)(an + (unsigned)(pS * NBINS + ok[e]) * AST +
                                           (cS0 + e) * 2) = 0;
                }
                uchar4 nb = *(const uchar4*)(binp + pS * TT + t0 + CK + cS0);
                const unsigned char* nk = (const unsigned char*)&nb;
                #pragma unroll
                for (int e = 0; e < 4; ++e)
                    *(unsigned short*)(an + (unsigned)(pS * NBINS + nk[e]) * AST +
                                       (cS0 + e) * 2) = ONE_F16;
            }
            storeB_item(smem, pf0, tid, nbuf);
            if (tid < 448) storeB_item(smem, pf1, tid + 512, nbuf);
        }
        __syncthreads();
    }

    // ---- K-split reduction (deterministic, stride-33 conflict-free) ----
    const int rrow = lane >> 2, rcol = (lane & 3) * 2;
    if (kg) {
        float* dst = (float*)smem + (unsigned)(kg - 1) * DRED_STRIDE;
        #pragma unroll
        for (int mt = 0; mt < 3; ++mt)
            #pragma unroll
            for (int nt = 0; nt < 4; ++nt) {
                const int row = mg * 48 + mt * 16 + rrow, col = nt * 8 + rcol;
                dst[row * 33 + col]           = acc[mt][nt][0];
                dst[row * 33 + col + 1]       = acc[mt][nt][1];
                dst[(row + 8) * 33 + col]     = acc[mt][nt][2];
                dst[(row + 8) * 33 + col + 1] = acc[mt][nt][3];
            }
    }
    __syncthreads();
    if (!kg) {
        float* Dfin = (float*)(smem + DFIN_OFF);
        const float* dr = (const float*)smem;
        #pragma unroll
        for (int mt = 0; mt < 3; ++mt)
            #pragma unroll
            for (int nt = 0; nt < 4; ++nt) {
                const int row = mg * 48 + mt * 16 + rrow, col = nt * 8 + rcol;
                const int i0 = row * 33 + col, i2 = (row + 8) * 33 + col;
                Dfin[i0]     = acc[mt][nt][0] + dr[i0] + dr[DRED_STRIDE + i0] + dr[2*DRED_STRIDE + i0];
                Dfin[i0 + 1] = acc[mt][nt][1] + dr[i0+1] + dr[DRED_STRIDE + i0+1] + dr[2*DRED_STRIDE + i0+1];
                Dfin[i2]     = acc[mt][nt][2] + dr[i2] + dr[DRED_STRIDE + i2] + dr[2*DRED_STRIDE + i2];
                Dfin[i2 + 1] = acc[mt][nt][3] + dr[i2+1] + dr[DRED_STRIDE + i2+1] + dr[2*DRED_STRIDE + i2+1];
            }
    }
    __syncthreads();

    // ---- epilogue per (p,a); counts in col 30 ----
    if (tid < FP * FA) {
        const float* Dfin = (const float*)(smem + DFIN_OFF);
        const int p = tid / FA;
        const int a = tid - p * FA;
        float meanv[NBINS];
        float tot = 0.f;
        #pragma unroll
        for (int k = 0; k < NBINS; ++k) {
            const float sv = Dfin[(p * NBINS + k) * 33 + a];
            const float cf = Dfin[(p * NBINS + k) * 33 + 30];
            const float m = sv / (cf + 1e-9f);
            meanv[k] = m;
            tot += m;
        }
        const float inv = 1.0f / (tot + 1e-9f);
        float ent = 0.f;
        #pragma unroll
        for (int k = 0; k < NBINS; ++k) {
            const float pr = meanv[k] * inv;
            ent += pr * logf(pr + 1e-9f);
        }
        const float L18 = 2.8903717578961645f;  // log(18)
        g_partial[((long)(bc * FP + p) * FA + a) * SSEG + s] = (L18 + ent) / L18;
    }
}

__global__ void mi_mean_kernel(float* __restrict__ out)
{
    int i = blockIdx.x * blockDim.x + threadIdx.x;
    if (i < BB*CC*FP*FA) {
        const float* p = g_partial + (long)i * SSEG;
        out[i] = (p[0] + p[1] + p[2] + p[3]) * 0.25f;
    }
}

extern "C" void kernel_launch(void* const* d_in, const int* in_sizes, int n_in,
                              void* d_out, int out_size)
{
    const float* pha = (const float*)d_in[0];
    const float* amp = (const float*)d_in[1];
    if (n_in >= 2 && in_sizes[0] > in_sizes[1]) {   // defensive: pha is smaller
        const float* t = pha; pha = amp; amp = t;
    }
    (void)cudaFuncSetAttribute(mi_mma_kernel,
                               cudaFuncAttributeMaxDynamicSharedMemorySize, SMEM_BYTES);
    mi_mma_kernel<<<BB*CC*SSEG, NTH, SMEM_BYTES>>>(pha, amp);
    mi_mean_kernel<<<(BB*CC*FP*FA + 255) / 256, 256>>>((float*)d_out);
}